// round 15
// baseline (speedup 1.0000x reference)
#include <cuda_runtime.h>
#include <cuda_fp16.h>
#include <stdint.h>
#include <math.h>

#define BATCH 16
#define CH    512
#define DD    4096

// ------------------- scratch (__device__ globals) -------------------
__device__ __half g_qh[BATCH * CH * DD];   // x1 fp16 [b][c][d]
__device__ __half g_kh[BATCH * CH * DD];   // x2 fp16 [b][e][d]
__device__ float  g_S [BATCH * CH * CH];   // scores fp32 [b][c][e]
__device__ __half g_Pa[BATCH * CH * CH];   // row softmax fp16 [b][c][e]
__device__ __half g_Mn[BATCH * CH * CH];   // col softmax fp16 [b][c][e]

// ------------------- helpers -------------------
__device__ __forceinline__ unsigned smem_u32(const void* p) {
    unsigned a;
    asm("{ .reg .u64 t; cvta.to.shared.u64 t, %1; cvt.u32.u64 %0, t; }" : "=r"(a) : "l"(p));
    return a;
}

#define CPA16(dst, src)  asm volatile("cp.async.cg.shared.global [%0], [%1], 16;" :: "r"(dst), "l"(src) : "memory")
#define CPA_COMMIT()     asm volatile("cp.async.commit_group;" ::: "memory")
#define CPA_WAITG(n)     asm volatile("cp.async.wait_group %0;" :: "n"(n) : "memory")

#define LDSM_X4(r, a) asm volatile(                                    \
    "ldmatrix.sync.aligned.m8n8.x4.shared.b16 {%0,%1,%2,%3}, [%4];"    \
    : "=r"((r)[0]), "=r"((r)[1]), "=r"((r)[2]), "=r"((r)[3]) : "r"(a))
#define LDSM_X4T(r, a) asm volatile(                                   \
    "ldmatrix.sync.aligned.m8n8.x4.trans.shared.b16 {%0,%1,%2,%3}, [%4];" \
    : "=r"((r)[0]), "=r"((r)[1]), "=r"((r)[2]), "=r"((r)[3]) : "r"(a))

__device__ __forceinline__ void mma16816(float* c, const unsigned* a,
                                         unsigned b0, unsigned b1) {
    asm volatile(
        "mma.sync.aligned.m16n8k16.row.col.f32.f16.f16.f32 "
        "{%0,%1,%2,%3}, {%4,%5,%6,%7}, {%8,%9}, {%0,%1,%2,%3};"
        : "+f"(c[0]), "+f"(c[1]), "+f"(c[2]), "+f"(c[3])
        : "r"(a[0]), "r"(a[1]), "r"(a[2]), "r"(a[3]), "r"(b0), "r"(b1));
}

// ------------------- fp32 -> fp16 cast -------------------
__global__ void __launch_bounds__(256)
convert_cast(const float* __restrict__ x1, const float* __restrict__ x2,
             __half* __restrict__ qh, __half* __restrict__ kh)
{
    const long base   = (long)blockIdx.x * 256 + threadIdx.x;
    const long stride = 8192L * 256;
    float4 v1[4], v2[4];
#pragma unroll
    for (int t = 0; t < 4; t++) {
        v1[t] = ((const float4*)x1)[base + t * stride];
        v2[t] = ((const float4*)x2)[base + t * stride];
    }
#pragma unroll
    for (int t = 0; t < 4; t++) {
        __half2 a0 = __floats2half2_rn(v1[t].x, v1[t].y), a1 = __floats2half2_rn(v1[t].z, v1[t].w);
        __half2 b0 = __floats2half2_rn(v2[t].x, v2[t].y), b1 = __floats2half2_rn(v2[t].z, v2[t].w);
        uint2 o1 = { *(unsigned*)&a0, *(unsigned*)&a1 };
        uint2 o2 = { *(unsigned*)&b0, *(unsigned*)&b1 };
        ((uint2*)qh)[base + t * stride] = o1;
        ((uint2*)kh)[base + t * stride] = o2;
    }
}

// ------------------- HMMA fp16 GEMM (R7/R11 config, verbatim) -------------------
#define BK      32
#define ROWMK   80
#define ROWKN   272
#define NSTAGE  4

template<int LAY> struct TileBytes { static const int v = 128 * ROWMK; };  // 10240
template<> struct TileBytes<1>     { static const int v = BK * ROWKN;  };  // 8704

template<int ALAY, int BLAY>
__global__ void __launch_bounds__(128, 2)
gemm_mma(const __half* __restrict__ A, const __half* __restrict__ B, float* __restrict__ C,
         int K, int lda, int ldb, int ldc,
         long sA, long sB, long sC, float scale)
{
    constexpr int ATB = TileBytes<ALAY>::v;
    constexpr int BTB = TileBytes<BLAY>::v;
    constexpr int STG = ATB + BTB;

    extern __shared__ char smem[];
    const unsigned sb = smem_u32(smem);

    const int tid  = threadIdx.x;
    const int wid  = tid >> 5, lane = tid & 31;
    const int wm   = wid & 1, wn = wid >> 1;

    const int m0 = blockIdx.y * 128, n0 = blockIdx.x * 128;
    const __half* Ab = A + (long)blockIdx.z * sA + (ALAY == 0 ? (long)m0 * lda : (long)m0);
    const __half* Bb = B + (long)blockIdx.z * sB + (BLAY == 0 ? (long)n0 * ldb : (long)n0);

    auto load_tile = [&](const __half* G, int ld, int kt, unsigned dstBase, int lay) {
#pragma unroll
        for (int h = 0; h < 4; h++) {
            int i = tid + h * 128;
            if (lay == 0) {
                int row = i >> 2, c = i & 3;
                CPA16(dstBase + (unsigned)(row * ROWMK + c * 16),
                      (const char*)(G + (long)row * ld + kt * BK) + c * 16);
            } else {
                int row = i >> 4, c = i & 15;
                CPA16(dstBase + (unsigned)(row * ROWKN + c * 16),
                      (const char*)(G + (long)(kt * BK + row) * ld) + c * 16);
            }
        }
    };
    auto load_stage = [&](int kt, int s) {
        const unsigned base = sb + (unsigned)s * STG;
        load_tile(Ab, lda, kt, base, ALAY);
        load_tile(Bb, ldb, kt, base + ATB, BLAY);
    };

    unsigned a_off, b_off;
    if (ALAY == 0)
        a_off = (unsigned)((wm * 64 + (lane & 15)) * ROWMK + ((lane >> 4) & 1) * 16);
    else
        a_off = (unsigned)(((lane & 7) + ((lane >> 4) & 1) * 8) * ROWKN
                           + (wm * 64 + ((lane >> 3) & 1) * 8) * 2);
    if (BLAY == 0)
        b_off = (unsigned)(ATB + (wn * 64 + (lane & 7) + ((lane >> 4) & 1) * 8) * ROWMK
                           + ((lane >> 3) & 1) * 16);
    else
        b_off = (unsigned)(ATB + ((lane & 7) + ((lane >> 3) & 1) * 8) * ROWKN
                           + (wn * 64 + ((lane >> 4) & 1) * 8) * 2);

    float acc[4][8][4];
#pragma unroll
    for (int i = 0; i < 4; i++)
#pragma unroll
        for (int j = 0; j < 8; j++)
#pragma unroll
            for (int v = 0; v < 4; v++) acc[i][j][v] = 0.f;

    const int NT = K / BK;
    load_stage(0, 0); CPA_COMMIT();
    load_stage(1, 1); CPA_COMMIT();
    load_stage(2, 2); CPA_COMMIT();

    for (int kt = 0; kt < NT; kt++) {
        CPA_WAITG(2);
        __syncthreads();
        if (kt + 3 < NT) load_stage(kt + 3, (kt + 3) & (NSTAGE - 1));
        CPA_COMMIT();

        const unsigned stg = sb + (unsigned)(kt & (NSTAGE - 1)) * STG;
#pragma unroll
        for (int ks = 0; ks < 2; ks++) {
            unsigned af[4][4], bf[4][4];
#pragma unroll
            for (int mi = 0; mi < 4; mi++) {
                if (ALAY == 0)
                    LDSM_X4(af[mi], stg + a_off + (unsigned)(mi * 16 * ROWMK + ks * 32));
                else
                    LDSM_X4T(af[mi], stg + a_off + (unsigned)(ks * 16 * ROWKN + mi * 32));
            }
#pragma unroll
            for (int nt = 0; nt < 4; nt++) {
                if (BLAY == 0)
                    LDSM_X4(bf[nt], stg + b_off + (unsigned)(nt * 16 * ROWMK + ks * 32));
                else
                    LDSM_X4T(bf[nt], stg + b_off + (unsigned)(ks * 16 * ROWKN + nt * 32));
            }
#pragma unroll
            for (int mi = 0; mi < 4; mi++)
#pragma unroll
                for (int n8 = 0; n8 < 8; n8++) {
                    const unsigned* bp = bf[n8 >> 1];
                    mma16816(acc[mi][n8], af[mi],
                             bp[(n8 & 1) * 2], bp[(n8 & 1) * 2 + 1]);
                }
        }
    }

    float* Cb = C + (long)blockIdx.z * sC
                  + (long)(m0 + wm * 64) * ldc + n0 + wn * 64;
    const int r0 = lane >> 2, c0 = (lane & 3) * 2;
#pragma unroll
    for (int mi = 0; mi < 4; mi++) {
#pragma unroll
        for (int n8 = 0; n8 < 8; n8++) {
            float* p = Cb + (long)(mi * 16 + r0) * ldc + n8 * 8 + c0;
            float2 v0 = { acc[mi][n8][0] * scale, acc[mi][n8][1] * scale };
            float2 v1 = { acc[mi][n8][2] * scale, acc[mi][n8][3] * scale };
            *(float2*)p = v0;
            *(float2*)(p + 8 * (long)ldc) = v1;
        }
    }
}

// ------------------- row softmax: vectorized (float2 in, half2 out) -------------------
// 256 threads; thread t handles elements 2t, 2t+1 of one row.
__global__ void __launch_bounds__(256)
row_softmax_k(const float* __restrict__ S, __half* __restrict__ Pa)
{
    const int b = blockIdx.y, r = blockIdx.x;
    const float* row = S + ((long)b * CH + r) * CH;
    __half* prow = Pa + ((long)b * CH + r) * CH;
    const int tid = threadIdx.x;

    float2 v = ((const float2*)row)[tid];
    float m = fmaxf(v.x, v.y);
#pragma unroll
    for (int o = 16; o > 0; o >>= 1) m = fmaxf(m, __shfl_xor_sync(0xffffffffu, m, o));

    __shared__ float red[8];
    if ((tid & 31) == 0) red[tid >> 5] = m;
    __syncthreads();
    float mall = red[0];
#pragma unroll
    for (int w = 1; w < 8; w++) mall = fmaxf(mall, red[w]);

    float e0 = expf(v.x - mall), e1 = expf(v.y - mall);
    float s = e0 + e1;
#pragma unroll
    for (int o = 16; o > 0; o >>= 1) s += __shfl_xor_sync(0xffffffffu, s, o);
    __syncthreads();
    if ((tid & 31) == 0) red[tid >> 5] = s;
    __syncthreads();
    float sall = 0.f;
#pragma unroll
    for (int w = 0; w < 8; w++) sall += red[w];

    float inv = 1.0f / sall;
    ((__half2*)prow)[tid] = __floats2half2_rn(e0 * inv, e1 * inv);
}

// ------------------- col softmax: register-cached S values (read S once) -------------------
// 512 thr = 64 e-lanes x 8 c-groups of 64; grid 128 blocks (< 148 SMs, 1 wave).
__global__ void __launch_bounds__(512)
col_softmax_k(const float* __restrict__ S, __half* __restrict__ Mn)
{
    const int idx  = blockIdx.x;
    const int b    = idx >> 3;
    const int tid  = threadIdx.x;
    const int lane = tid & 63;
    const int g    = tid >> 6;
    const int e    = (idx & 7) * 64 + lane;

    const float* Sb = S + (long)b * CH * CH;
    __half* Mb = Mn + (long)b * CH * CH;

    float vals[64];
    float m = -INFINITY, s = 0.f;
#pragma unroll
    for (int j = 0; j < 64; j += 4) {
        int c = g * 64 + j;
        float v0 = Sb[(long)(c + 0) * CH + e];
        float v1 = Sb[(long)(c + 1) * CH + e];
        float v2 = Sb[(long)(c + 2) * CH + e];
        float v3 = Sb[(long)(c + 3) * CH + e];
        vals[j] = v0; vals[j + 1] = v1; vals[j + 2] = v2; vals[j + 3] = v3;
        float mn   = fmaxf(fmaxf(v0, v1), fmaxf(v2, v3));
        float mnew = fmaxf(m, mn);
        s = s * expf(m - mnew)
          + expf(v0 - mnew) + expf(v1 - mnew) + expf(v2 - mnew) + expf(v3 - mnew);
        m = mnew;
    }

    __shared__ float sm[8][64];
    __shared__ float ss[8][64];
    sm[g][lane] = m;
    ss[g][lane] = s;
    __syncthreads();

    float M = -INFINITY, Sv = 0.f;
#pragma unroll
    for (int gi = 0; gi < 8; gi++) {
        float mg = sm[gi][lane], sg = ss[gi][lane];
        float Mn2 = fmaxf(M, mg);
        Sv = Sv * expf(M - Mn2) + sg * expf(mg - Mn2);
        M = Mn2;
    }
    float inv = 1.0f / Sv;

#pragma unroll
    for (int j = 0; j < 64; j++) {
        int c = g * 64 + j;
        Mb[(long)c * CH + e] = __float2half_rn(expf(vals[j] - M) * inv);
    }
}

// ------------------- launcher -------------------
extern "C" void kernel_launch(void* const* d_in, const int* in_sizes, int n_in,
                              void* d_out, int out_size)
{
    const float* x1 = (const float*)d_in[0];
    const float* x2 = (const float*)d_in[1];
    float* outA = (float*)d_out;
    float* outB = outA + (long)BATCH * CH * DD;

    __half *qh, *kh, *Pa, *Mn;
    float *S;
    cudaGetSymbolAddress((void**)&qh, g_qh);
    cudaGetSymbolAddress((void**)&kh, g_kh);
    cudaGetSymbolAddress((void**)&S,  g_S);
    cudaGetSymbolAddress((void**)&Pa, g_Pa);
    cudaGetSymbolAddress((void**)&Mn, g_Mn);

    constexpr int SM00 = NSTAGE * (TileBytes<0>::v + TileBytes<0>::v);  // 81920
    constexpr int SM01 = NSTAGE * (TileBytes<0>::v + TileBytes<1>::v);  // 75776
    constexpr int SM11 = NSTAGE * (TileBytes<1>::v + TileBytes<1>::v);  // 69632
    cudaFuncSetAttribute(gemm_mma<0, 0>, cudaFuncAttributeMaxDynamicSharedMemorySize, SM00);
    cudaFuncSetAttribute(gemm_mma<0, 1>, cudaFuncAttributeMaxDynamicSharedMemorySize, SM01);
    cudaFuncSetAttribute(gemm_mma<1, 1>, cudaFuncAttributeMaxDynamicSharedMemorySize, SM11);

    // 0) fp32 -> fp16 cast
    convert_cast<<<8192, 256>>>(x1, x2, qh, kh);

    // 1) S = (1/64) * q @ k^T     M=512 N=512 K=4096
    gemm_mma<0, 0><<<dim3(CH / 128, CH / 128, BATCH), 128, SM00>>>(
        qh, kh, S, DD, DD, DD, CH,
        (long)CH * DD, (long)CH * DD, (long)CH * CH, 1.0f / 64.0f);

    // 2) softmaxes (col first: long blocks, no tail)
    col_softmax_k<<<128, 512>>>(S, Mn);
    row_softmax_k<<<dim3(CH, BATCH), 256>>>(S, Pa);

    // 3) outA = Pa @ k            M=512 N=4096 K=512
    gemm_mma<0, 1><<<dim3(DD / 128, CH / 128, BATCH), 128, SM01>>>(
        Pa, kh, outA, CH, CH, DD, DD,
        (long)CH * CH, (long)CH * DD, (long)CH * DD, 1.0f);

    // 4) outB = Mn^T @ q          M=512(e) N=4096(d) K=512(c)
    gemm_mma<1, 1><<<dim3(DD / 128, CH / 128, BATCH), 128, SM11>>>(
        Mn, qh, outB, CH, CH, DD, DD,
        (long)CH * CH, (long)CH * DD, (long)CH * DD, 1.0f);
}

// round 16
// speedup vs baseline: 1.4396x; 1.4396x over previous
#include <cuda_runtime.h>
#include <cuda_fp16.h>
#include <stdint.h>
#include <math.h>

#define BATCH 16
#define CH    512
#define DD    4096

// ------------------- scratch (__device__ globals) -------------------
__device__ __half g_qh[BATCH * CH * DD];   // x1 fp16 [b][c][d]
__device__ __half g_kh[BATCH * CH * DD];   // x2 fp16 [b][e][d]
__device__ float  g_S [BATCH * CH * CH];   // scores fp32 [b][c][e]
__device__ __half g_Pa[BATCH * CH * CH];   // row softmax fp16 [b][c][e]
__device__ __half g_Mn[BATCH * CH * CH];   // col softmax fp16 [b][c][e]

// ------------------- helpers -------------------
__device__ __forceinline__ unsigned smem_u32(const void* p) {
    unsigned a;
    asm("{ .reg .u64 t; cvta.to.shared.u64 t, %1; cvt.u32.u64 %0, t; }" : "=r"(a) : "l"(p));
    return a;
}

#define CPA16(dst, src)  asm volatile("cp.async.cg.shared.global [%0], [%1], 16;" :: "r"(dst), "l"(src) : "memory")
#define CPA_COMMIT()     asm volatile("cp.async.commit_group;" ::: "memory")
#define CPA_WAITG(n)     asm volatile("cp.async.wait_group %0;" :: "n"(n) : "memory")

#define LDSM_X4(r, a) asm volatile(                                    \
    "ldmatrix.sync.aligned.m8n8.x4.shared.b16 {%0,%1,%2,%3}, [%4];"    \
    : "=r"((r)[0]), "=r"((r)[1]), "=r"((r)[2]), "=r"((r)[3]) : "r"(a))
#define LDSM_X4T(r, a) asm volatile(                                   \
    "ldmatrix.sync.aligned.m8n8.x4.trans.shared.b16 {%0,%1,%2,%3}, [%4];" \
    : "=r"((r)[0]), "=r"((r)[1]), "=r"((r)[2]), "=r"((r)[3]) : "r"(a))

__device__ __forceinline__ void mma16816(float* c, const unsigned* a,
                                         unsigned b0, unsigned b1) {
    asm volatile(
        "mma.sync.aligned.m16n8k16.row.col.f32.f16.f16.f32 "
        "{%0,%1,%2,%3}, {%4,%5,%6,%7}, {%8,%9}, {%0,%1,%2,%3};"
        : "+f"(c[0]), "+f"(c[1]), "+f"(c[2]), "+f"(c[3])
        : "r"(a[0]), "r"(a[1]), "r"(a[2]), "r"(a[3]), "r"(b0), "r"(b1));
}

// ------------------- fp32 -> fp16 cast -------------------
__global__ void __launch_bounds__(256)
convert_cast(const float* __restrict__ x1, const float* __restrict__ x2,
             __half* __restrict__ qh, __half* __restrict__ kh)
{
    const long base   = (long)blockIdx.x * 256 + threadIdx.x;
    const long stride = 8192L * 256;
    float4 v1[4], v2[4];
#pragma unroll
    for (int t = 0; t < 4; t++) {
        v1[t] = ((const float4*)x1)[base + t * stride];
        v2[t] = ((const float4*)x2)[base + t * stride];
    }
#pragma unroll
    for (int t = 0; t < 4; t++) {
        __half2 a0 = __floats2half2_rn(v1[t].x, v1[t].y), a1 = __floats2half2_rn(v1[t].z, v1[t].w);
        __half2 b0 = __floats2half2_rn(v2[t].x, v2[t].y), b1 = __floats2half2_rn(v2[t].z, v2[t].w);
        uint2 o1 = { *(unsigned*)&a0, *(unsigned*)&a1 };
        uint2 o2 = { *(unsigned*)&b0, *(unsigned*)&b1 };
        ((uint2*)qh)[base + t * stride] = o1;
        ((uint2*)kh)[base + t * stride] = o2;
    }
}

// ------------------- HMMA fp16 GEMM (R7 config, NSTAGE=5) -------------------
#define BK      32
#define ROWMK   80
#define ROWKN   272
#define NSTAGE  5

template<int LAY> struct TileBytes { static const int v = 128 * ROWMK; };  // 10240
template<> struct TileBytes<1>     { static const int v = BK * ROWKN;  };  // 8704

template<int ALAY, int BLAY>
__global__ void __launch_bounds__(128, 2)
gemm_mma(const __half* __restrict__ A, const __half* __restrict__ B, float* __restrict__ C,
         int K, int lda, int ldb, int ldc,
         long sA, long sB, long sC, float scale)
{
    constexpr int ATB = TileBytes<ALAY>::v;
    constexpr int BTB = TileBytes<BLAY>::v;
    constexpr int STG = ATB + BTB;

    extern __shared__ char smem[];
    const unsigned sb = smem_u32(smem);

    const int tid  = threadIdx.x;
    const int wid  = tid >> 5, lane = tid & 31;
    const int wm   = wid & 1, wn = wid >> 1;

    const int m0 = blockIdx.y * 128, n0 = blockIdx.x * 128;
    const __half* Ab = A + (long)blockIdx.z * sA + (ALAY == 0 ? (long)m0 * lda : (long)m0);
    const __half* Bb = B + (long)blockIdx.z * sB + (BLAY == 0 ? (long)n0 * ldb : (long)n0);

    auto load_tile = [&](const __half* G, int ld, int kt, unsigned dstBase, int lay) {
#pragma unroll
        for (int h = 0; h < 4; h++) {
            int i = tid + h * 128;
            if (lay == 0) {
                int row = i >> 2, c = i & 3;
                CPA16(dstBase + (unsigned)(row * ROWMK + c * 16),
                      (const char*)(G + (long)row * ld + kt * BK) + c * 16);
            } else {
                int row = i >> 4, c = i & 15;
                CPA16(dstBase + (unsigned)(row * ROWKN + c * 16),
                      (const char*)(G + (long)(kt * BK + row) * ld) + c * 16);
            }
        }
    };
    auto load_stage = [&](int kt, int s) {
        const unsigned base = sb + (unsigned)s * STG;
        load_tile(Ab, lda, kt, base, ALAY);
        load_tile(Bb, ldb, kt, base + ATB, BLAY);
    };

    unsigned a_off, b_off;
    if (ALAY == 0)
        a_off = (unsigned)((wm * 64 + (lane & 15)) * ROWMK + ((lane >> 4) & 1) * 16);
    else
        a_off = (unsigned)(((lane & 7) + ((lane >> 4) & 1) * 8) * ROWKN
                           + (wm * 64 + ((lane >> 3) & 1) * 8) * 2);
    if (BLAY == 0)
        b_off = (unsigned)(ATB + (wn * 64 + (lane & 7) + ((lane >> 4) & 1) * 8) * ROWMK
                           + ((lane >> 3) & 1) * 16);
    else
        b_off = (unsigned)(ATB + ((lane & 7) + ((lane >> 3) & 1) * 8) * ROWKN
                           + (wn * 64 + ((lane >> 4) & 1) * 8) * 2);

    float acc[4][8][4];
#pragma unroll
    for (int i = 0; i < 4; i++)
#pragma unroll
        for (int j = 0; j < 8; j++)
#pragma unroll
            for (int v = 0; v < 4; v++) acc[i][j][v] = 0.f;

    const int NT = K / BK;
    load_stage(0, 0); CPA_COMMIT();
    load_stage(1, 1); CPA_COMMIT();
    load_stage(2, 2); CPA_COMMIT();
    load_stage(3, 3); CPA_COMMIT();

    int s_load = 4, s_comp = 0;
    for (int kt = 0; kt < NT; kt++) {
        CPA_WAITG(3);
        __syncthreads();
        if (kt + 4 < NT) load_stage(kt + 4, s_load);
        CPA_COMMIT();
        if (++s_load == NSTAGE) s_load = 0;

        const unsigned stg = sb + (unsigned)s_comp * STG;
        if (++s_comp == NSTAGE) s_comp = 0;
#pragma unroll
        for (int ks = 0; ks < 2; ks++) {
            unsigned af[4][4], bf[4][4];
#pragma unroll
            for (int mi = 0; mi < 4; mi++) {
                if (ALAY == 0)
                    LDSM_X4(af[mi], stg + a_off + (unsigned)(mi * 16 * ROWMK + ks * 32));
                else
                    LDSM_X4T(af[mi], stg + a_off + (unsigned)(ks * 16 * ROWKN + mi * 32));
            }
#pragma unroll
            for (int nt = 0; nt < 4; nt++) {
                if (BLAY == 0)
                    LDSM_X4(bf[nt], stg + b_off + (unsigned)(nt * 16 * ROWMK + ks * 32));
                else
                    LDSM_X4T(bf[nt], stg + b_off + (unsigned)(ks * 16 * ROWKN + nt * 32));
            }
#pragma unroll
            for (int mi = 0; mi < 4; mi++)
#pragma unroll
                for (int n8 = 0; n8 < 8; n8++) {
                    const unsigned* bp = bf[n8 >> 1];
                    mma16816(acc[mi][n8], af[mi],
                             bp[(n8 & 1) * 2], bp[(n8 & 1) * 2 + 1]);
                }
        }
    }

    float* Cb = C + (long)blockIdx.z * sC
                  + (long)(m0 + wm * 64) * ldc + n0 + wn * 64;
    const int r0 = lane >> 2, c0 = (lane & 3) * 2;
#pragma unroll
    for (int mi = 0; mi < 4; mi++) {
#pragma unroll
        for (int n8 = 0; n8 < 8; n8++) {
            float* p = Cb + (long)(mi * 16 + r0) * ldc + n8 * 8 + c0;
            float2 v0 = { acc[mi][n8][0] * scale, acc[mi][n8][1] * scale };
            float2 v1 = { acc[mi][n8][2] * scale, acc[mi][n8][3] * scale };
            *(float2*)p = v0;
            *(float2*)(p + 8 * (long)ldc) = v1;
        }
    }
}

// ------------------- row softmax: vectorized (verified safe in R15) -------------------
__global__ void __launch_bounds__(256)
row_softmax_k(const float* __restrict__ S, __half* __restrict__ Pa)
{
    const int b = blockIdx.y, r = blockIdx.x;
    const float* row = S + ((long)b * CH + r) * CH;
    __half* prow = Pa + ((long)b * CH + r) * CH;
    const int tid = threadIdx.x;

    float2 v = ((const float2*)row)[tid];
    float m = fmaxf(v.x, v.y);
#pragma unroll
    for (int o = 16; o > 0; o >>= 1) m = fmaxf(m, __shfl_xor_sync(0xffffffffu, m, o));

    __shared__ float red[8];
    if ((tid & 31) == 0) red[tid >> 5] = m;
    __syncthreads();
    float mall = red[0];
#pragma unroll
    for (int w = 1; w < 8; w++) mall = fmaxf(mall, red[w]);

    float e0 = expf(v.x - mall), e1 = expf(v.y - mall);
    float s = e0 + e1;
#pragma unroll
    for (int o = 16; o > 0; o >>= 1) s += __shfl_xor_sync(0xffffffffu, s, o);
    __syncthreads();
    if ((tid & 31) == 0) red[tid >> 5] = s;
    __syncthreads();
    float sall = 0.f;
#pragma unroll
    for (int w = 0; w < 8; w++) sall += red[w];

    float inv = 1.0f / sall;
    ((__half2*)prow)[tid] = __floats2half2_rn(e0 * inv, e1 * inv);
}

// ------------------- col softmax (R7 config, verbatim) -------------------
__global__ void col_softmax_k(const float* __restrict__ S, __half* __restrict__ Mn)
{
    const int b    = blockIdx.y;
    const int tid  = threadIdx.x;      // 512
    const int lane = tid & 63;
    const int g    = tid >> 6;         // c-group 0..7
    const int e    = blockIdx.x * 64 + lane;

    const float* Sb = S + (long)b * CH * CH;
    __half* Mb = Mn + (long)b * CH * CH;

    float m = -INFINITY, s = 0.f;
    for (int c = g * 64; c < g * 64 + 64; c += 4) {
        float v0 = Sb[(long)(c + 0) * CH + e];
        float v1 = Sb[(long)(c + 1) * CH + e];
        float v2 = Sb[(long)(c + 2) * CH + e];
        float v3 = Sb[(long)(c + 3) * CH + e];
        float mn   = fmaxf(fmaxf(v0, v1), fmaxf(v2, v3));
        float mnew = fmaxf(m, mn);
        s = s * expf(m - mnew)
          + expf(v0 - mnew) + expf(v1 - mnew) + expf(v2 - mnew) + expf(v3 - mnew);
        m = mnew;
    }

    __shared__ float sm[8][64];
    __shared__ float ss[8][64];
    sm[g][lane] = m;
    ss[g][lane] = s;
    __syncthreads();

    float M = -INFINITY, Sv = 0.f;
#pragma unroll
    for (int gi = 0; gi < 8; gi++) {
        float mg = sm[gi][lane], sg = ss[gi][lane];
        float Mn2 = fmaxf(M, mg);
        Sv = Sv * expf(M - Mn2) + sg * expf(mg - Mn2);
        M = Mn2;
    }
    float inv = 1.0f / Sv;

    for (int c = g * 64; c < g * 64 + 64; c++) {
        Mb[(long)c * CH + e] = __float2half_rn(expf(Sb[(long)c * CH + e] - M) * inv);
    }
}

// ------------------- launcher -------------------
extern "C" void kernel_launch(void* const* d_in, const int* in_sizes, int n_in,
                              void* d_out, int out_size)
{
    const float* x1 = (const float*)d_in[0];
    const float* x2 = (const float*)d_in[1];
    float* outA = (float*)d_out;
    float* outB = outA + (long)BATCH * CH * DD;

    __half *qh, *kh, *Pa, *Mn;
    float *S;
    cudaGetSymbolAddress((void**)&qh, g_qh);
    cudaGetSymbolAddress((void**)&kh, g_kh);
    cudaGetSymbolAddress((void**)&S,  g_S);
    cudaGetSymbolAddress((void**)&Pa, g_Pa);
    cudaGetSymbolAddress((void**)&Mn, g_Mn);

    constexpr int SM00 = NSTAGE * (TileBytes<0>::v + TileBytes<0>::v);  // 102400
    constexpr int SM01 = NSTAGE * (TileBytes<0>::v + TileBytes<1>::v);  // 94720
    constexpr int SM11 = NSTAGE * (TileBytes<1>::v + TileBytes<1>::v);  // 87040
    cudaFuncSetAttribute(gemm_mma<0, 0>, cudaFuncAttributeMaxDynamicSharedMemorySize, SM00);
    cudaFuncSetAttribute(gemm_mma<0, 1>, cudaFuncAttributeMaxDynamicSharedMemorySize, SM01);
    cudaFuncSetAttribute(gemm_mma<1, 1>, cudaFuncAttributeMaxDynamicSharedMemorySize, SM11);

    // 0) fp32 -> fp16 cast
    convert_cast<<<8192, 256>>>(x1, x2, qh, kh);

    // 1) S = (1/64) * q @ k^T     M=512 N=512 K=4096
    gemm_mma<0, 0><<<dim3(CH / 128, CH / 128, BATCH), 128, SM00>>>(
        qh, kh, S, DD, DD, DD, CH,
        (long)CH * DD, (long)CH * DD, (long)CH * CH, 1.0f / 64.0f);

    // 2) softmaxes
    row_softmax_k<<<dim3(CH, BATCH), 256>>>(S, Pa);
    col_softmax_k<<<dim3(CH / 64, BATCH), 512>>>(S, Mn);

    // 3) outA = Pa @ k            M=512 N=4096 K=512
    gemm_mma<0, 1><<<dim3(DD / 128, CH / 128, BATCH), 128, SM01>>>(
        Pa, kh, outA, CH, CH, DD, DD,
        (long)CH * CH, (long)CH * DD, (long)CH * DD, 1.0f);

    // 4) outB = Mn^T @ q          M=512(e) N=4096(d) K=512(c)
    gemm_mma<1, 1><<<dim3(DD / 128, CH / 128, BATCH), 128, SM11>>>(
        Mn, qh, outB, CH, CH, DD, DD,
        (long)CH * CH, (long)CH * DD, (long)CH * DD, 1.0f);
}